// round 1
// baseline (speedup 1.0000x reference)
#include <cuda_runtime.h>
#include <math.h>

#define N_NODES 100000
#define E_EDGES 3200000
#define F_IN    256
#define D_OUT   128

// ---------------- static scratch (no cudaMalloc allowed) ----------------
__device__ float g_u[F_IN];
__device__ float g_v[F_IN];
__device__ float g_sa1[N_NODES];
__device__ float g_sa2[N_NODES];
__device__ int   g_rowptr[N_NODES + 1];
__device__ float g_value[(size_t)N_NODES * D_OUT];   // 51.2 MB, fits L2

// ---------------- tiny: u = W1 @ w2, v = W1 @ w3 ----------------
__global__ void uv_kernel(const float* __restrict__ W1,
                          const float* __restrict__ w2,
                          const float* __restrict__ w3) {
    int t = threadIdx.x;                 // 256 threads, t = F_IN row
    float su = 0.f, sv = 0.f;
    #pragma unroll 8
    for (int d = 0; d < D_OUT; d++) {
        float w = W1[t * D_OUT + d];
        su += w * w2[d];
        sv += w * w3[d];
    }
    g_u[t] = su;
    g_v[t] = sv;
}

// ---------------- sa1/sa2: one warp per node ----------------
__global__ __launch_bounds__(256) void sa_kernel(const float* __restrict__ x,
                                                 const float* __restrict__ b2,
                                                 const float* __restrict__ b3) {
    __shared__ float su[F_IN], sv[F_IN];
    int tid = threadIdx.x;
    su[tid] = g_u[tid];
    sv[tid] = g_v[tid];
    __syncthreads();

    int warp = tid >> 5, lane = tid & 31;
    int node = blockIdx.x * 8 + warp;
    if (node >= N_NODES) return;

    const float* xr = x + (size_t)node * F_IN;
    float s1 = 0.f, s2 = 0.f;
    #pragma unroll
    for (int s = 0; s < 8; s++) {
        float xv = xr[lane + 32 * s];
        s1 += xv * su[lane + 32 * s];
        s2 += xv * sv[lane + 32 * s];
    }
    #pragma unroll
    for (int o = 16; o; o >>= 1) {
        s1 += __shfl_xor_sync(0xffffffffu, s1, o);
        s2 += __shfl_xor_sync(0xffffffffu, s2, o);
    }
    if (lane == 0) {
        g_sa1[node] = s1 + b2[0];
        g_sa2[node] = s2 + b3[0];
    }
}

// ---------------- row_ptr by binary search (edge_row is sorted) ----------------
__global__ void rowptr_kernel(const int* __restrict__ er) {
    int i = blockIdx.x * blockDim.x + threadIdx.x;
    if (i > N_NODES) return;
    int lo = 0, hi = E_EDGES;
    while (lo < hi) {
        int mid = (lo + hi) >> 1;
        if (er[mid] < i) lo = mid + 1; else hi = mid;
    }
    g_rowptr[i] = lo;
}

// ---------------- SGEMM: value = x @ kernel  (M=100000, N=128, K=256) ----------------
#define BM 128
#define BN 128
#define BK 16

__global__ __launch_bounds__(256) void sgemm_kernel(const float* __restrict__ A,
                                                    const float* __restrict__ B,
                                                    float* __restrict__ C,
                                                    int M) {
    __shared__ float As[BK][BM];   // transposed tile
    __shared__ float Bs[BK][BN];

    const int tid = threadIdx.x;
    const int block_row = blockIdx.x * BM;
    const int ty = tid >> 4;   // 0..15
    const int tx = tid & 15;   // 0..15

    float acc[8][8];
    #pragma unroll
    for (int i = 0; i < 8; i++)
        #pragma unroll
        for (int j = 0; j < 8; j++) acc[i][j] = 0.f;

    for (int k0 = 0; k0 < F_IN; k0 += BK) {
        // A tile: 128 rows x 16 k, float4 along K, stored transposed
        #pragma unroll
        for (int r = 0; r < 2; r++) {
            int idx = tid + r * 256;          // 0..511
            int row = idx >> 2;               // 0..127
            int kq  = (idx & 3) << 2;         // 0,4,8,12
            int grow = block_row + row;
            float4 av = (grow < M)
                ? *(const float4*)(A + (size_t)grow * F_IN + k0 + kq)
                : make_float4(0.f, 0.f, 0.f, 0.f);
            As[kq + 0][row] = av.x;
            As[kq + 1][row] = av.y;
            As[kq + 2][row] = av.z;
            As[kq + 3][row] = av.w;
        }
        // B tile: 16 k-rows x 128 n, float4 along N
        #pragma unroll
        for (int r = 0; r < 2; r++) {
            int idx  = tid + r * 256;
            int krow = idx >> 5;              // 0..15
            int nq   = (idx & 31) << 2;       // 0..124
            *(float4*)(&Bs[krow][nq]) =
                *(const float4*)(B + (size_t)(k0 + krow) * BN + nq);
        }
        __syncthreads();

        #pragma unroll
        for (int k = 0; k < BK; k++) {
            float a[8], b[8];
            *(float4*)(a)     = *(const float4*)(&As[k][ty * 8]);
            *(float4*)(a + 4) = *(const float4*)(&As[k][ty * 8 + 4]);
            *(float4*)(b)     = *(const float4*)(&Bs[k][tx * 8]);
            *(float4*)(b + 4) = *(const float4*)(&Bs[k][tx * 8 + 4]);
            #pragma unroll
            for (int i = 0; i < 8; i++)
                #pragma unroll
                for (int j = 0; j < 8; j++)
                    acc[i][j] += a[i] * b[j];
        }
        __syncthreads();
    }

    #pragma unroll
    for (int i = 0; i < 8; i++) {
        int grow = block_row + ty * 8 + i;
        if (grow < M) {
            float4 v0 = make_float4(acc[i][0], acc[i][1], acc[i][2], acc[i][3]);
            float4 v1 = make_float4(acc[i][4], acc[i][5], acc[i][6], acc[i][7]);
            *(float4*)(C + (size_t)grow * BN + tx * 8)     = v0;
            *(float4*)(C + (size_t)grow * BN + tx * 8 + 4) = v1;
        }
    }
}

// ---------------- fused softmax + SpMM: one warp per row ----------------
__global__ __launch_bounds__(256) void spmm_kernel(const float* __restrict__ adj,
                                                   const int* __restrict__ col,
                                                   const float* __restrict__ bias,
                                                   float* __restrict__ out) {
    int warp = threadIdx.x >> 5, lane = threadIdx.x & 31;
    int row = blockIdx.x * 8 + warp;
    if (row >= N_NODES) return;

    int start = g_rowptr[row];
    int end   = g_rowptr[row + 1];
    float sa1r = g_sa1[row];

    // pass 1: segment max of leaky-relu'd logits
    float m = -INFINITY;
    for (int j = start + lane; j < end; j += 32) {
        float a = adj[j];
        int   c = col[j];
        float e = a * (sa1r + g_sa2[c]);
        e = e > 0.f ? e : 0.2f * e;
        m = fmaxf(m, e);
    }
    #pragma unroll
    for (int o = 16; o; o >>= 1)
        m = fmaxf(m, __shfl_xor_sync(0xffffffffu, m, o));

    // pass 2: exp + denom + unnormalized aggregate
    float4 acc = make_float4(0.f, 0.f, 0.f, 0.f);
    float dsum = 0.f;
    for (int base = start; base < end; base += 32) {
        int j = base + lane;
        float ex = 0.f;
        int   c  = 0;
        if (j < end) {
            float a = adj[j];
            c = col[j];
            float e = a * (sa1r + g_sa2[c]);
            e = e > 0.f ? e : 0.2f * e;
            ex = __expf(e - m);
        }
        dsum += ex;
        int cnt = min(32, end - base);
        for (int t = 0; t < cnt; ++t) {
            float exj = __shfl_sync(0xffffffffu, ex, t);
            int   cj  = __shfl_sync(0xffffffffu, c,  t);
            const float4 vv =
                *(const float4*)(g_value + (size_t)cj * D_OUT + lane * 4);
            acc.x += exj * vv.x;
            acc.y += exj * vv.y;
            acc.z += exj * vv.z;
            acc.w += exj * vv.w;
        }
    }
    #pragma unroll
    for (int o = 16; o; o >>= 1)
        dsum += __shfl_xor_sync(0xffffffffu, dsum, o);
    if (dsum <= 0.f) dsum = 1.0f;
    float inv = 1.0f / dsum;

    const float4 bv = *(const float4*)(bias + (size_t)row * D_OUT + lane * 4);
    float4 ov;
    ov.x = acc.x * inv + bv.x;
    ov.y = acc.y * inv + bv.y;
    ov.z = acc.z * inv + bv.z;
    ov.w = acc.w * inv + bv.w;
    *(float4*)(out + (size_t)row * D_OUT + lane * 4) = ov;
}

// ---------------- launch ----------------
extern "C" void kernel_launch(void* const* d_in, const int* in_sizes, int n_in,
                              void* d_out, int out_size) {
    const float* x        = (const float*)d_in[0];   // [N, 256]
    const float* adj_val  = (const float*)d_in[1];   // [E]
    const float* W1       = (const float*)d_in[2];   // [256, 128]
    const float* w2       = (const float*)d_in[3];   // [128, 1]
    const float* b2       = (const float*)d_in[4];   // [1]
    const float* w3       = (const float*)d_in[5];   // [128, 1]
    const float* b3       = (const float*)d_in[6];   // [1]
    const float* kern     = (const float*)d_in[7];   // [256, 128]
    const float* bias     = (const float*)d_in[8];   // [N, 128]
    const int*   edge_row = (const int*)d_in[9];     // [E] sorted
    const int*   edge_col = (const int*)d_in[10];    // [E]
    float* out = (float*)d_out;                      // [N, 128]

    float* value;
    cudaGetSymbolAddress((void**)&value, g_value);

    uv_kernel<<<1, 256>>>(W1, w2, w3);
    sa_kernel<<<(N_NODES + 7) / 8, 256>>>(x, b2, b3);
    rowptr_kernel<<<(N_NODES + 1 + 255) / 256, 256>>>(edge_row);
    sgemm_kernel<<<(N_NODES + BM - 1) / BM, 256>>>(x, kern, value, N_NODES);
    spmm_kernel<<<(N_NODES + 7) / 8, 256>>>(adj_val, edge_col, bias, out);
}

// round 3
// speedup vs baseline: 1.0790x; 1.0790x over previous
#include <cuda_runtime.h>
#include <cuda_bf16.h>
#include <math.h>
#include <stdint.h>

#define N_NODES 100000
#define E_EDGES 3200000
#define F_IN    256
#define D_OUT   128

// ---------------- static scratch (no cudaMalloc allowed) ----------------
__device__ float g_u[F_IN];
__device__ float g_v[F_IN];
__device__ float g_sa1[N_NODES];
__device__ float g_sa2[N_NODES];
__device__ int   g_rowptr[N_NODES + 1];
__device__ float g_value[(size_t)N_NODES * D_OUT];   // 51.2 MB, fits L2
// Plain [n][k] bf16 hi/lo images of B = kernel^T (n = out col, k = in feature)
__device__ __nv_bfloat16 g_Bhi[D_OUT * F_IN];        // 64 KB
__device__ __nv_bfloat16 g_Blo[D_OUT * F_IN];        // 64 KB

// ---------------- helpers ----------------
__device__ __forceinline__ void cvt_pair(float x, float y, uint32_t& hi, uint32_t& lo) {
    __nv_bfloat16 hx = __float2bfloat16_rn(x);
    __nv_bfloat16 hy = __float2bfloat16_rn(y);
    hi = (uint32_t)__bfloat16_as_ushort(hx) | ((uint32_t)__bfloat16_as_ushort(hy) << 16);
    __nv_bfloat16 lx = __float2bfloat16_rn(x - __bfloat162float(hx));
    __nv_bfloat16 ly = __float2bfloat16_rn(y - __bfloat162float(hy));
    lo = (uint32_t)__bfloat16_as_ushort(lx) | ((uint32_t)__bfloat16_as_ushort(ly) << 16);
}

__device__ __forceinline__ void mma16816(float* c, const uint32_t* a, uint32_t b0, uint32_t b1) {
    asm volatile(
        "mma.sync.aligned.m16n8k16.row.col.f32.bf16.bf16.f32 "
        "{%0,%1,%2,%3}, {%4,%5,%6,%7}, {%8,%9}, {%0,%1,%2,%3};"
        : "+f"(c[0]), "+f"(c[1]), "+f"(c[2]), "+f"(c[3])
        : "r"(a[0]), "r"(a[1]), "r"(a[2]), "r"(a[3]), "r"(b0), "r"(b1));
}

// ---------------- tiny: u = W1 @ w2, v = W1 @ w3 ----------------
__global__ void uv_kernel(const float* __restrict__ W1,
                          const float* __restrict__ w2,
                          const float* __restrict__ w3) {
    int t = threadIdx.x;
    float su = 0.f, sv = 0.f;
    #pragma unroll 8
    for (int d = 0; d < D_OUT; d++) {
        float w = W1[t * D_OUT + d];
        su += w * w2[d];
        sv += w * w3[d];
    }
    g_u[t] = su;
    g_v[t] = sv;
}

// ---------------- B prep: kernel[k][n] -> plain [n][k] bf16 hi/lo ----------------
__global__ void bprep_kernel(const float* __restrict__ kern) {
    int idx = blockIdx.x * blockDim.x + threadIdx.x;   // 0..32767
    if (idx >= F_IN * D_OUT) return;
    int k = idx >> 7;          // 0..255
    int n = idx & 127;         // 0..127
    float v = kern[k * D_OUT + n];
    __nv_bfloat16 h = __float2bfloat16_rn(v);
    __nv_bfloat16 l = __float2bfloat16_rn(v - __bfloat162float(h));
    g_Bhi[n * F_IN + k] = h;
    g_Blo[n * F_IN + k] = l;
}

// ---------------- sa1/sa2: one warp per node ----------------
__global__ __launch_bounds__(256) void sa_kernel(const float* __restrict__ x,
                                                 const float* __restrict__ b2,
                                                 const float* __restrict__ b3) {
    __shared__ float su[F_IN], sv[F_IN];
    int tid = threadIdx.x;
    su[tid] = g_u[tid];
    sv[tid] = g_v[tid];
    __syncthreads();

    int warp = tid >> 5, lane = tid & 31;
    int node = blockIdx.x * 8 + warp;
    if (node >= N_NODES) return;

    const float* xr = x + (size_t)node * F_IN;
    float s1 = 0.f, s2 = 0.f;
    #pragma unroll
    for (int s = 0; s < 8; s++) {
        float xv = xr[lane + 32 * s];
        s1 += xv * su[lane + 32 * s];
        s2 += xv * sv[lane + 32 * s];
    }
    #pragma unroll
    for (int o = 16; o; o >>= 1) {
        s1 += __shfl_xor_sync(0xffffffffu, s1, o);
        s2 += __shfl_xor_sync(0xffffffffu, s2, o);
    }
    if (lane == 0) {
        g_sa1[node] = s1 + b2[0];
        g_sa2[node] = s2 + b3[0];
    }
}

// ---------------- row_ptr by binary search (edge_row is sorted) ----------------
__global__ void rowptr_kernel(const int* __restrict__ er) {
    int i = blockIdx.x * blockDim.x + threadIdx.x;
    if (i > N_NODES) return;
    int lo = 0, hi = E_EDGES;
    while (lo < hi) {
        int mid = (lo + hi) >> 1;
        if (er[mid] < i) lo = mid + 1; else hi = mid;
    }
    g_rowptr[i] = lo;
}

// ---------------- HMMA GEMM: value = x @ kernel (M=100000, N=128, K=256) ----------------
// bf16 hi/lo split: C = Ah*Bh + Ah*Bl + Al*Bh, fp32 accumulate.
// 256 threads = 8 warps (2x4), warp tile 64x32, CTA tile 128x128, K in 16 steps of 16.
// B in SMEM with padded stride (264 bf16 = 132 words/row) -> conflict-free LDS.32.
#define SPADW 132                          // u32 words per B row in smem
#define SMEM_B_BYTES (2 * 128 * SPADW * 4) // hi + lo = 135168 B

__global__ void __launch_bounds__(256, 1)
mma_gemm(const float* __restrict__ A, float* __restrict__ C, int M) {
    extern __shared__ uint32_t sB[];       // [hi|lo][128][SPADW]
    int tid = threadIdx.x;

    // Copy preconverted B into padded smem
    {
        const uint32_t* bh = (const uint32_t*)g_Bhi;
        const uint32_t* bl = (const uint32_t*)g_Blo;
        #pragma unroll 4
        for (int i = tid; i < 128 * 128; i += 256) {
            int n = i >> 7, kk = i & 127;
            sB[n * SPADW + kk] = bh[i];
            sB[128 * SPADW + n * SPADW + kk] = bl[i];
        }
    }
    __syncthreads();

    int wid = tid >> 5, lane = tid & 31;
    int wr = wid >> 2, wc = wid & 3;       // warp grid 2 x 4
    int lg = lane >> 2, lq = lane & 3;     // group (0..7), quad (0..3)
    int mbase = blockIdx.x * 128 + wr * 64;
    int nbase = wc * 32;
    int kq = lq * 2;

    float acc[4][4][4];
    #pragma unroll
    for (int i = 0; i < 4; i++)
        #pragma unroll
        for (int j = 0; j < 4; j++)
            #pragma unroll
            for (int q = 0; q < 4; q++) acc[i][j][q] = 0.f;

    #pragma unroll 1
    for (int ks = 0; ks < 16; ks++) {
        int k0 = ks * 16;

        // A fragments for 4 m-tiles: hi & lo, 4 regs each
        uint32_t ah[4][4], al[4][4];
        #pragma unroll
        for (int mt = 0; mt < 4; mt++) {
            int r0 = mbase + mt * 16 + lg;
            int r1 = r0 + 8;
            if (r0 >= M) r0 = M - 1;       // clamp: garbage rows computed, never stored
            if (r1 >= M) r1 = M - 1;
            const float* p0 = A + (size_t)r0 * F_IN + k0 + kq;
            const float* p1 = A + (size_t)r1 * F_IN + k0 + kq;
            float2 v00 = *(const float2*)(p0);
            float2 v10 = *(const float2*)(p1);
            float2 v01 = *(const float2*)(p0 + 8);
            float2 v11 = *(const float2*)(p1 + 8);
            cvt_pair(v00.x, v00.y, ah[mt][0], al[mt][0]);
            cvt_pair(v10.x, v10.y, ah[mt][1], al[mt][1]);
            cvt_pair(v01.x, v01.y, ah[mt][2], al[mt][2]);
            cvt_pair(v11.x, v11.y, ah[mt][3], al[mt][3]);
        }

        // B fragments for 4 n-tiles (hi & lo)
        uint32_t bh0[4], bh1[4], bl0[4], bl1[4];
        #pragma unroll
        for (int nt = 0; nt < 4; nt++) {
            int n0 = nbase + nt * 8 + lg;
            uint32_t off = (uint32_t)n0 * SPADW + (uint32_t)((k0 + kq) >> 1);
            bh0[nt] = sB[off];
            bh1[nt] = sB[off + 4];
            bl0[nt] = sB[128 * SPADW + off];
            bl1[nt] = sB[128 * SPADW + off + 4];
        }

        // Term-major MMA order: dependent MMAs on same acc are 16 issues apart
        #pragma unroll
        for (int mt = 0; mt < 4; mt++)
            #pragma unroll
            for (int nt = 0; nt < 4; nt++)
                mma16816(acc[mt][nt], ah[mt], bh0[nt], bh1[nt]);
        #pragma unroll
        for (int mt = 0; mt < 4; mt++)
            #pragma unroll
            for (int nt = 0; nt < 4; nt++)
                mma16816(acc[mt][nt], ah[mt], bl0[nt], bl1[nt]);
        #pragma unroll
        for (int mt = 0; mt < 4; mt++)
            #pragma unroll
            for (int nt = 0; nt < 4; nt++)
                mma16816(acc[mt][nt], al[mt], bh0[nt], bh1[nt]);
    }

    // Epilogue: direct float2 stores
    #pragma unroll
    for (int mt = 0; mt < 4; mt++) {
        int r0 = mbase + mt * 16 + lg;
        #pragma unroll
        for (int nt = 0; nt < 4; nt++) {
            int col = nbase + nt * 8 + kq;
            if (r0 < M)
                *(float2*)(C + (size_t)r0 * D_OUT + col) =
                    make_float2(acc[mt][nt][0], acc[mt][nt][1]);
            if (r0 + 8 < M)
                *(float2*)(C + (size_t)(r0 + 8) * D_OUT + col) =
                    make_float2(acc[mt][nt][2], acc[mt][nt][3]);
        }
    }
}

// ---------------- fused softmax + SpMM: one warp per row ----------------
__global__ __launch_bounds__(256) void spmm_kernel(const float* __restrict__ adj,
                                                   const int* __restrict__ col,
                                                   const float* __restrict__ bias,
                                                   float* __restrict__ out) {
    int warp = threadIdx.x >> 5, lane = threadIdx.x & 31;
    int row = blockIdx.x * 8 + warp;
    if (row >= N_NODES) return;

    int start = g_rowptr[row];
    int end   = g_rowptr[row + 1];
    float sa1r = g_sa1[row];

    // pass 1: segment max of leaky-relu'd logits
    float m = -INFINITY;
    for (int j = start + lane; j < end; j += 32) {
        float a = adj[j];
        int   c = col[j];
        float e = a * (sa1r + g_sa2[c]);
        e = e > 0.f ? e : 0.2f * e;
        m = fmaxf(m, e);
    }
    #pragma unroll
    for (int o = 16; o; o >>= 1)
        m = fmaxf(m, __shfl_xor_sync(0xffffffffu, m, o));

    // pass 2: exp + denom + unnormalized aggregate
    float4 acc = make_float4(0.f, 0.f, 0.f, 0.f);
    float dsum = 0.f;
    for (int base = start; base < end; base += 32) {
        int j = base + lane;
        float ex = 0.f;
        int   c  = 0;
        if (j < end) {
            float a = adj[j];
            c = col[j];
            float e = a * (sa1r + g_sa2[c]);
            e = e > 0.f ? e : 0.2f * e;
            ex = __expf(e - m);
        }
        dsum += ex;
        int cnt = min(32, end - base);
        for (int t = 0; t < cnt; ++t) {
            float exj = __shfl_sync(0xffffffffu, ex, t);
            int   cj  = __shfl_sync(0xffffffffu, c,  t);
            const float4 vv =
                *(const float4*)(g_value + (size_t)cj * D_OUT + lane * 4);
            acc.x += exj * vv.x;
            acc.y += exj * vv.y;
            acc.z += exj * vv.z;
            acc.w += exj * vv.w;
        }
    }
    #pragma unroll
    for (int o = 16; o; o >>= 1)
        dsum += __shfl_xor_sync(0xffffffffu, dsum, o);
    if (dsum <= 0.f) dsum = 1.0f;
    float inv = 1.0f / dsum;

    const float4 bv = *(const float4*)(bias + (size_t)row * D_OUT + lane * 4);
    float4 ov;
    ov.x = acc.x * inv + bv.x;
    ov.y = acc.y * inv + bv.y;
    ov.z = acc.z * inv + bv.z;
    ov.w = acc.w * inv + bv.w;
    *(float4*)(out + (size_t)row * D_OUT + lane * 4) = ov;
}

// ---------------- launch ----------------
extern "C" void kernel_launch(void* const* d_in, const int* in_sizes, int n_in,
                              void* d_out, int out_size) {
    const float* x        = (const float*)d_in[0];   // [N, 256]
    const float* adj_val  = (const float*)d_in[1];   // [E]
    const float* W1       = (const float*)d_in[2];   // [256, 128]
    const float* w2       = (const float*)d_in[3];   // [128, 1]
    const float* b2       = (const float*)d_in[4];   // [1]
    const float* w3       = (const float*)d_in[5];   // [128, 1]
    const float* b3       = (const float*)d_in[6];   // [1]
    const float* kern     = (const float*)d_in[7];   // [256, 128]
    const float* bias     = (const float*)d_in[8];   // [N, 128]
    const int*   edge_row = (const int*)d_in[9];     // [E] sorted
    const int*   edge_col = (const int*)d_in[10];    // [E]
    float* out = (float*)d_out;                      // [N, 128]

    float* value;
    cudaGetSymbolAddress((void**)&value, g_value);

    cudaFuncSetAttribute(mma_gemm, cudaFuncAttributeMaxDynamicSharedMemorySize, SMEM_B_BYTES);

    uv_kernel<<<1, 256>>>(W1, w2, w3);
    bprep_kernel<<<(F_IN * D_OUT + 255) / 256, 256>>>(kern);
    sa_kernel<<<(N_NODES + 7) / 8, 256>>>(x, b2, b3);
    rowptr_kernel<<<(N_NODES + 1 + 255) / 256, 256>>>(edge_row);
    mma_gemm<<<(N_NODES + 127) / 128, 256, SMEM_B_BYTES>>>(x, value, N_NODES);
    spmm_kernel<<<(N_NODES + 7) / 8, 256>>>(adj_val, edge_col, bias, out);
}

// round 5
// speedup vs baseline: 1.1981x; 1.1104x over previous
#include <cuda_runtime.h>
#include <cuda_bf16.h>
#include <cuda_fp16.h>
#include <math.h>
#include <stdint.h>

#define N_NODES 100000
#define E_EDGES 3200000
#define F_IN    256
#define D_OUT   128

// ---------------- static scratch (no cudaMalloc allowed) ----------------
__device__ float g_u[F_IN];
__device__ float g_v[F_IN];
__device__ float g_sa1[N_NODES];
__device__ float g_sa2[N_NODES];
__device__ float g_vscale[N_NODES];
__device__ int   g_rowptr[N_NODES + 1];
__device__ short g_qval[(size_t)N_NODES * D_OUT];    // 25.6 MB int16 value, fits L2
// Plain [n][k] bf16 hi/lo images of B = kernel^T
__device__ __nv_bfloat16 g_Bhi[D_OUT * F_IN];        // 64 KB
__device__ __nv_bfloat16 g_Blo[D_OUT * F_IN];        // 64 KB

// ---------------- helpers ----------------
__device__ __forceinline__ void cvt_pair(float x, float y, uint32_t& hi, uint32_t& lo) {
    __nv_bfloat16 hx = __float2bfloat16_rn(x);
    __nv_bfloat16 hy = __float2bfloat16_rn(y);
    hi = (uint32_t)__bfloat16_as_ushort(hx) | ((uint32_t)__bfloat16_as_ushort(hy) << 16);
    __nv_bfloat16 lx = __float2bfloat16_rn(x - __bfloat162float(hx));
    __nv_bfloat16 ly = __float2bfloat16_rn(y - __bfloat162float(hy));
    lo = (uint32_t)__bfloat16_as_ushort(lx) | ((uint32_t)__bfloat16_as_ushort(ly) << 16);
}

__device__ __forceinline__ void mma16816(float* c, const uint32_t* a, uint32_t b0, uint32_t b1) {
    asm volatile(
        "mma.sync.aligned.m16n8k16.row.col.f32.bf16.bf16.f32 "
        "{%0,%1,%2,%3}, {%4,%5,%6,%7}, {%8,%9}, {%0,%1,%2,%3};"
        : "+f"(c[0]), "+f"(c[1]), "+f"(c[2]), "+f"(c[3])
        : "r"(a[0]), "r"(a[1]), "r"(a[2]), "r"(a[3]), "r"(b0), "r"(b1));
}

// ---------------- prep: uv (block 0) + B conversion ----------------
__global__ void prep_kernel(const float* __restrict__ kern,
                            const float* __restrict__ W1,
                            const float* __restrict__ w2,
                            const float* __restrict__ w3) {
    int idx = blockIdx.x * blockDim.x + threadIdx.x;   // 0..32767
    if (idx < F_IN * D_OUT) {
        int k = idx >> 7;
        int n = idx & 127;
        float v = kern[k * D_OUT + n];
        __nv_bfloat16 h = __float2bfloat16_rn(v);
        __nv_bfloat16 l = __float2bfloat16_rn(v - __bfloat162float(h));
        g_Bhi[n * F_IN + k] = h;
        g_Blo[n * F_IN + k] = l;
    }
    if (blockIdx.x == 0) {
        int t = threadIdx.x;
        float su = 0.f, sv = 0.f;
        #pragma unroll 8
        for (int d = 0; d < D_OUT; d++) {
            float w = W1[t * D_OUT + d];
            su += w * w2[d];
            sv += w * w3[d];
        }
        g_u[t] = su;
        g_v[t] = sv;
    }
}

// ---------------- row_ptr by boundary scatter (edge_row is sorted) ----------------
__global__ void rowptr_kernel(const int* __restrict__ er) {
    int j = blockIdx.x * blockDim.x + threadIdx.x;
    if (j > E_EDGES) return;
    int hi = (j == E_EDGES) ? N_NODES : er[j];
    int lo = (j == 0) ? -1 : er[j - 1];
    for (int i = lo + 1; i <= hi; i++) g_rowptr[i] = j;
}

// ---------------- HMMA GEMM + fused sa + int16 quantize epilogue ----------------
// value = x @ kernel (bf16 hi/lo split, fp32 acc), sa1/sa2 = x@u+b2, x@v+b3.
// Output: per-row int16 q + scale (value ≈ s_row * q).
#define SPADW 132                          // u32 words per B row in smem
#define APADW 20                           // u32 words per A row per chunk
#define SM_BHI_W 0
#define SM_BLO_W (128 * SPADW)
#define SM_AHI_W (2 * 128 * SPADW)
#define SM_ALO_W (SM_AHI_W + 128 * APADW)
#define SM_U_W   (SM_ALO_W + 128 * APADW)
#define SM_V_W   (SM_U_W + 256)
#define SMEM_WORDS (SM_V_W + 256)
#define SMEM_BYTES (SMEM_WORDS * 4)        // 157,696 B
// epilogue reuse (B region is dead after the k-loop):
#define CPADW 132                          // fp32 C buffer stride (words)
#define SM_PMAX_W (128 * CPADW + 64)       // 256 floats of partial max

__global__ void __launch_bounds__(256, 1)
mma_gemm(const float* __restrict__ A, short* __restrict__ Q,
         const float* __restrict__ b2, const float* __restrict__ b3, int M) {
    extern __shared__ uint32_t sm[];
    int tid = threadIdx.x;

    // preload B (padded) and u/v
    {
        const uint4* bh = (const uint4*)g_Bhi;
        const uint4* bl = (const uint4*)g_Blo;
        #pragma unroll
        for (int r = 0; r < 16; r++) {
            int i = tid + r * 256;            // 0..4095 uint4
            int n = i >> 5, w = i & 31;
            *(uint4*)(sm + SM_BHI_W + n * SPADW + w * 4) = bh[i];
            *(uint4*)(sm + SM_BLO_W + n * SPADW + w * 4) = bl[i];
        }
        sm[SM_U_W + tid] = ((const uint32_t*)g_u)[tid];
        sm[SM_V_W + tid] = ((const uint32_t*)g_v)[tid];
    }
    __syncthreads();

    const float* sU = (const float*)(sm + SM_U_W);
    const float* sV = (const float*)(sm + SM_V_W);

    int wid = tid >> 5, lane = tid & 31;
    int wr = wid >> 2, wc = wid & 3;       // warp grid 2 x 4
    int lg = lane >> 2, lq = lane & 3;     // group (0..7), quad (0..3)
    long base = (long)blockIdx.x * 128;
    int nbase = wc * 32;
    int kq = lq * 2;

    int srow_g = tid >> 3;                 // 0..31
    int skk = (tid & 7) * 4;               // 0,4,..,28

    float acc[4][4][4];
    #pragma unroll
    for (int i = 0; i < 4; i++)
        #pragma unroll
        for (int j = 0; j < 4; j++)
            #pragma unroll
            for (int q = 0; q < 4; q++) acc[i][j][q] = 0.f;

    float s1[4] = {0.f, 0.f, 0.f, 0.f}, s2[4] = {0.f, 0.f, 0.f, 0.f};

    #pragma unroll 1
    for (int c = 0; c < 8; ++c) {
        int k0 = c * 32;
        // stage A chunk: load fp32 once, convert, accumulate sa
        #pragma unroll
        for (int it = 0; it < 4; ++it) {
            int row = it * 32 + srow_g;
            long grow = base + row;
            if (grow >= M) grow = M - 1;
            float4 a = *(const float4*)(A + grow * F_IN + k0 + skk);
            s1[it] += a.x * sU[k0 + skk] + a.y * sU[k0 + skk + 1]
                    + a.z * sU[k0 + skk + 2] + a.w * sU[k0 + skk + 3];
            s2[it] += a.x * sV[k0 + skk] + a.y * sV[k0 + skk + 1]
                    + a.z * sV[k0 + skk + 2] + a.w * sV[k0 + skk + 3];
            uint32_t h0, l0, h1, l1;
            cvt_pair(a.x, a.y, h0, l0);
            cvt_pair(a.z, a.w, h1, l1);
            int wbase = row * APADW + (skk >> 1);
            *(uint2*)(sm + SM_AHI_W + wbase) = make_uint2(h0, h1);
            *(uint2*)(sm + SM_ALO_W + wbase) = make_uint2(l0, l1);
        }
        __syncthreads();

        #pragma unroll
        for (int ksi = 0; ksi < 2; ++ksi) {
            uint32_t ah[4][4], al[4][4];
            #pragma unroll
            for (int mt = 0; mt < 4; mt++) {
                int r0 = wr * 64 + mt * 16 + lg;
                int w0 = r0 * APADW + ksi * 8 + lq;
                int w1 = (r0 + 8) * APADW + ksi * 8 + lq;
                ah[mt][0] = sm[SM_AHI_W + w0];
                ah[mt][1] = sm[SM_AHI_W + w1];
                ah[mt][2] = sm[SM_AHI_W + w0 + 4];
                ah[mt][3] = sm[SM_AHI_W + w1 + 4];
                al[mt][0] = sm[SM_ALO_W + w0];
                al[mt][1] = sm[SM_ALO_W + w1];
                al[mt][2] = sm[SM_ALO_W + w0 + 4];
                al[mt][3] = sm[SM_ALO_W + w1 + 4];
            }
            uint32_t bh0[4], bh1[4], bl0[4], bl1[4];
            int kglob = k0 + ksi * 16;
            #pragma unroll
            for (int nt = 0; nt < 4; nt++) {
                int n0 = nbase + nt * 8 + lg;
                uint32_t off = (uint32_t)n0 * SPADW + (uint32_t)((kglob + kq) >> 1);
                bh0[nt] = sm[SM_BHI_W + off];
                bh1[nt] = sm[SM_BHI_W + off + 4];
                bl0[nt] = sm[SM_BLO_W + off];
                bl1[nt] = sm[SM_BLO_W + off + 4];
            }
            #pragma unroll
            for (int mt = 0; mt < 4; mt++)
                #pragma unroll
                for (int nt = 0; nt < 4; nt++)
                    mma16816(acc[mt][nt], ah[mt], bh0[nt], bh1[nt]);
            #pragma unroll
            for (int mt = 0; mt < 4; mt++)
                #pragma unroll
                for (int nt = 0; nt < 4; nt++)
                    mma16816(acc[mt][nt], ah[mt], bl0[nt], bl1[nt]);
            #pragma unroll
            for (int mt = 0; mt < 4; mt++)
                #pragma unroll
                for (int nt = 0; nt < 4; nt++)
                    mma16816(acc[mt][nt], al[mt], bh0[nt], bh1[nt]);
        }
        __syncthreads();
    }

    // sa reduce over the 8 staging threads per row
    {
        float bb2 = b2[0], bb3 = b3[0];
        #pragma unroll
        for (int it = 0; it < 4; ++it) {
            float a1 = s1[it], a2 = s2[it];
            #pragma unroll
            for (int o = 4; o; o >>= 1) {
                a1 += __shfl_xor_sync(0xffffffffu, a1, o);
                a2 += __shfl_xor_sync(0xffffffffu, a2, o);
            }
            if ((tid & 7) == 0) {
                long grow = base + it * 32 + srow_g;
                if (grow < M) {
                    g_sa1[grow] = a1 + bb2;
                    g_sa2[grow] = a2 + bb3;
                }
            }
        }
    }

    // ---- epilogue: dump acc to smem fp32 (reusing dead B region) ----
    float* cs = (float*)sm;   // [128][CPADW]
    #pragma unroll
    for (int mt = 0; mt < 4; mt++) {
        int r0 = wr * 64 + mt * 16 + lg;
        #pragma unroll
        for (int nt = 0; nt < 4; nt++) {
            int col = nbase + nt * 8 + kq;
            *(float2*)(cs + r0 * CPADW + col) =
                make_float2(acc[mt][nt][0], acc[mt][nt][1]);
            *(float2*)(cs + (r0 + 8) * CPADW + col) =
                make_float2(acc[mt][nt][2], acc[mt][nt][3]);
        }
    }
    __syncthreads();

    // ---- per-row absmax (2 threads per row), scale, int16 quantize ----
    {
        int row = tid >> 1, half = tid & 1;
        const float* cr = cs + row * CPADW + half * 64;
        float mx = 0.f;
        #pragma unroll 16
        for (int j = 0; j < 64; j++) mx = fmaxf(mx, fabsf(cr[j]));
        ((float*)(sm + SM_PMAX_W))[tid] = mx;
        __syncthreads();
        float rmx = fmaxf(((float*)(sm + SM_PMAX_W))[row * 2],
                          ((float*)(sm + SM_PMAX_W))[row * 2 + 1]);
        rmx = fmaxf(rmx, 1e-30f);
        long grow = base + row;
        if (half == 0 && grow < M) g_vscale[grow] = rmx * (1.0f / 32767.0f);
        float inv = 32767.0f / rmx;
        if (grow < M) {
            uint4* dst = (uint4*)(Q + (grow << 7) + half * 64);   // 8 shorts per uint4
            #pragma unroll
            for (int b8 = 0; b8 < 8; b8++) {
                short sv[8];
                #pragma unroll
                for (int j = 0; j < 8; j++)
                    sv[j] = (short)__float2int_rn(cr[b8 * 8 + j] * inv);
                dst[b8] = *(uint4*)sv;
            }
        }
    }
}

// ---------------- fused softmax + SpMM: one warp per row, int16 value ----------------
__global__ __launch_bounds__(256) void spmm_kernel(const float* __restrict__ adj,
                                                   const int* __restrict__ col,
                                                   const float* __restrict__ bias,
                                                   float* __restrict__ out) {
    int warp = threadIdx.x >> 5, lane = threadIdx.x & 31;
    int row = blockIdx.x * 8 + warp;
    if (row >= N_NODES) return;

    int start = g_rowptr[row];
    int end   = g_rowptr[row + 1];
    float sa1r = g_sa1[row];

    // pass 1: segment max of leaky-relu'd logits
    float m = -INFINITY;
    for (int j = start + lane; j < end; j += 32) {
        float a = adj[j];
        int   c = col[j];
        float e = a * (sa1r + g_sa2[c]);
        e = e > 0.f ? e : 0.2f * e;
        m = fmaxf(m, e);
    }
    #pragma unroll
    for (int o = 16; o; o >>= 1)
        m = fmaxf(m, __shfl_xor_sync(0xffffffffu, m, o));

    // pass 2: exp + denom + scaled int16 aggregate
    float4 acc = make_float4(0.f, 0.f, 0.f, 0.f);
    float dsum = 0.f;
    for (int base = start; base < end; base += 32) {
        int j = base + lane;
        float ex = 0.f, sc = 0.f;
        int   c  = 0;
        if (j < end) {
            float a = adj[j];
            c = col[j];
            float e = a * (sa1r + g_sa2[c]);
            e = e > 0.f ? e : 0.2f * e;
            ex = __expf(e - m);
            sc = g_vscale[c];
        }
        dsum += ex;
        int cnt = min(32, end - base);
        for (int t = 0; t < cnt; ++t) {
            float wj = __shfl_sync(0xffffffffu, ex, t) *
                       __shfl_sync(0xffffffffu, sc, t);
            int   cj = __shfl_sync(0xffffffffu, c, t);
            int2 raw = *(const int2*)(g_qval + ((size_t)cj << 7) + lane * 4);
            short2 p0 = *reinterpret_cast<short2*>(&raw.x);
            short2 p1 = *reinterpret_cast<short2*>(&raw.y);
            acc.x += wj * (float)p0.x;
            acc.y += wj * (float)p0.y;
            acc.z += wj * (float)p1.x;
            acc.w += wj * (float)p1.y;
        }
    }
    #pragma unroll
    for (int o = 16; o; o >>= 1)
        dsum += __shfl_xor_sync(0xffffffffu, dsum, o);
    if (dsum <= 0.f) dsum = 1.0f;
    float inv = 1.0f / dsum;

    const float4 bv = *(const float4*)(bias + (size_t)row * D_OUT + lane * 4);
    float4 ov;
    ov.x = acc.x * inv + bv.x;
    ov.y = acc.y * inv + bv.y;
    ov.z = acc.z * inv + bv.z;
    ov.w = acc.w * inv + bv.w;
    *(float4*)(out + (size_t)row * D_OUT + lane * 4) = ov;
}

// ---------------- launch ----------------
extern "C" void kernel_launch(void* const* d_in, const int* in_sizes, int n_in,
                              void* d_out, int out_size) {
    const float* x        = (const float*)d_in[0];
    const float* adj_val  = (const float*)d_in[1];
    const float* W1       = (const float*)d_in[2];
    const float* w2       = (const float*)d_in[3];
    const float* b2       = (const float*)d_in[4];
    const float* w3       = (const float*)d_in[5];
    const float* b3       = (const float*)d_in[6];
    const float* kern     = (const float*)d_in[7];
    const float* bias     = (const float*)d_in[8];
    const int*   edge_row = (const int*)d_in[9];
    const int*   edge_col = (const int*)d_in[10];
    float* out = (float*)d_out;

    short* qval;
    cudaGetSymbolAddress((void**)&qval, g_qval);

    cudaFuncSetAttribute(mma_gemm, cudaFuncAttributeMaxDynamicSharedMemorySize, SMEM_BYTES);

    prep_kernel<<<(F_IN * D_OUT + 255) / 256, 256>>>(kern, W1, w2, w3);
    rowptr_kernel<<<(E_EDGES + 1 + 255) / 256, 256>>>(edge_row);
    mma_gemm<<<(N_NODES + 127) / 128, 256, SMEM_BYTES>>>(x, qval, b2, b3, N_NODES);
    spmm_kernel<<<(N_NODES + 7) / 8, 256>>>(adj_val, edge_col, bias, out);
}

// round 6
// speedup vs baseline: 1.4216x; 1.1865x over previous
#include <cuda_runtime.h>
#include <cuda_bf16.h>
#include <cuda_fp16.h>
#include <math.h>
#include <stdint.h>

#define N_NODES 100000
#define E_EDGES 3200000
#define F_IN    256
#define D_OUT   128

// ---------------- static scratch (no cudaMalloc allowed) ----------------
__device__ float g_u[F_IN];
__device__ float g_v[F_IN];
__device__ float g_sa1[N_NODES];
__device__ float g_sa2[N_NODES];
__device__ float g_vscale[N_NODES];
__device__ int   g_rowptr[N_NODES + 1];
__device__ short g_qval[(size_t)N_NODES * D_OUT];    // 25.6 MB int16 value, fits L2
__device__ __nv_bfloat16 g_Bhi[D_OUT * F_IN];        // 64 KB, [n][k]
__device__ __nv_bfloat16 g_Blo[D_OUT * F_IN];        // 64 KB

// ---------------- helpers ----------------
__device__ __forceinline__ void cvt_pair(float x, float y, uint32_t& hi, uint32_t& lo) {
    __nv_bfloat16 hx = __float2bfloat16_rn(x);
    __nv_bfloat16 hy = __float2bfloat16_rn(y);
    hi = (uint32_t)__bfloat16_as_ushort(hx) | ((uint32_t)__bfloat16_as_ushort(hy) << 16);
    __nv_bfloat16 lx = __float2bfloat16_rn(x - __bfloat162float(hx));
    __nv_bfloat16 ly = __float2bfloat16_rn(y - __bfloat162float(hy));
    lo = (uint32_t)__bfloat16_as_ushort(lx) | ((uint32_t)__bfloat16_as_ushort(ly) << 16);
}

__device__ __forceinline__ void mma16816(float* c, const uint32_t* a, uint32_t b0, uint32_t b1) {
    asm volatile(
        "mma.sync.aligned.m16n8k16.row.col.f32.bf16.bf16.f32 "
        "{%0,%1,%2,%3}, {%4,%5,%6,%7}, {%8,%9}, {%0,%1,%2,%3};"
        : "+f"(c[0]), "+f"(c[1]), "+f"(c[2]), "+f"(c[3])
        : "r"(a[0]), "r"(a[1]), "r"(a[2]), "r"(a[3]), "r"(b0), "r"(b1));
}

// ---------------- prep: uv (block 0) + B conversion ----------------
__global__ void prep_kernel(const float* __restrict__ kern,
                            const float* __restrict__ W1,
                            const float* __restrict__ w2,
                            const float* __restrict__ w3) {
    int idx = blockIdx.x * blockDim.x + threadIdx.x;
    if (idx < F_IN * D_OUT) {
        int k = idx >> 7;
        int n = idx & 127;
        float v = kern[k * D_OUT + n];
        __nv_bfloat16 h = __float2bfloat16_rn(v);
        __nv_bfloat16 l = __float2bfloat16_rn(v - __bfloat162float(h));
        g_Bhi[n * F_IN + k] = h;
        g_Blo[n * F_IN + k] = l;
    }
    if (blockIdx.x == 0) {
        int t = threadIdx.x;
        float su = 0.f, sv = 0.f;
        #pragma unroll 8
        for (int d = 0; d < D_OUT; d++) {
            float w = W1[t * D_OUT + d];
            su += w * w2[d];
            sv += w * w3[d];
        }
        g_u[t] = su;
        g_v[t] = sv;
    }
}

// ---------------- row_ptr by boundary scatter ----------------
__global__ void rowptr_kernel(const int* __restrict__ er) {
    int j = blockIdx.x * blockDim.x + threadIdx.x;
    if (j > E_EDGES) return;
    int hi = (j == E_EDGES) ? N_NODES : er[j];
    int lo = (j == 0) ? -1 : er[j - 1];
    for (int i = lo + 1; i <= hi; i++) g_rowptr[i] = j;
}

// ---------------- HMMA GEMM, double-buffered A staging ----------------
#define SPADW 132
#define APADW 20
#define ABUF_W 5120                        // hi+lo per buffer (2*128*20)
#define SM_BHI_W 0
#define SM_BLO_W (128 * SPADW)             // 16896
#define SM_A_W   (2 * 128 * SPADW)         // 33792
#define SM_U_W   (SM_A_W + 2 * ABUF_W)     // 44032
#define SM_V_W   (SM_U_W + 256)
#define SMEM_WORDS (SM_V_W + 256)          // 44544
#define SMEM_BYTES (SMEM_WORDS * 4)        // 178176 B
#define CPADW 132
#define SM_PMAX_W SM_BLO_W                 // reuse B-lo region for partial max

__global__ void __launch_bounds__(256, 1)
mma_gemm(const float* __restrict__ A, short* __restrict__ Q,
         const float* __restrict__ b2, const float* __restrict__ b3, int M) {
    extern __shared__ uint32_t sm[];
    int tid = threadIdx.x;

    // preload B (padded) and u/v
    {
        const uint4* bh = (const uint4*)g_Bhi;
        const uint4* bl = (const uint4*)g_Blo;
        #pragma unroll
        for (int r = 0; r < 16; r++) {
            int i = tid + r * 256;
            int n = i >> 5, w = i & 31;
            *(uint4*)(sm + SM_BHI_W + n * SPADW + w * 4) = bh[i];
            *(uint4*)(sm + SM_BLO_W + n * SPADW + w * 4) = bl[i];
        }
        sm[SM_U_W + tid] = ((const uint32_t*)g_u)[tid];
        sm[SM_V_W + tid] = ((const uint32_t*)g_v)[tid];
    }
    __syncthreads();

    const float* sU = (const float*)(sm + SM_U_W);
    const float* sV = (const float*)(sm + SM_V_W);

    int wid = tid >> 5, lane = tid & 31;
    int wr = wid >> 2, wc = wid & 3;
    int lg = lane >> 2, lq = lane & 3;
    long base = (long)blockIdx.x * 128;
    int nbase = wc * 32;
    int kq = lq * 2;

    int srow_g = tid >> 3;                 // 0..31
    int skk = (tid & 7) * 4;               // 0..28

    float acc[4][4][4];
    #pragma unroll
    for (int i = 0; i < 4; i++)
        #pragma unroll
        for (int j = 0; j < 4; j++)
            #pragma unroll
            for (int q = 0; q < 4; q++) acc[i][j][q] = 0.f;

    float s1[4] = {0.f, 0.f, 0.f, 0.f}, s2[4] = {0.f, 0.f, 0.f, 0.f};
    float4 areg[4];

    auto load_chunk = [&](int k0) {
        #pragma unroll
        for (int it = 0; it < 4; ++it) {
            int row = it * 32 + srow_g;
            long grow = base + row;
            if (grow >= M) grow = M - 1;
            areg[it] = *(const float4*)(A + grow * F_IN + k0 + skk);
        }
    };
    auto store_chunk = [&](int k0, int bb) {
        uint32_t* ahi = sm + SM_A_W + bb * ABUF_W;
        uint32_t* alo = ahi + 2560;
        float u0 = sU[k0 + skk], u1 = sU[k0 + skk + 1],
              u2 = sU[k0 + skk + 2], u3 = sU[k0 + skk + 3];
        float v0 = sV[k0 + skk], v1 = sV[k0 + skk + 1],
              v2 = sV[k0 + skk + 2], v3 = sV[k0 + skk + 3];
        #pragma unroll
        for (int it = 0; it < 4; ++it) {
            int row = it * 32 + srow_g;
            float4 a = areg[it];
            s1[it] += a.x * u0 + a.y * u1 + a.z * u2 + a.w * u3;
            s2[it] += a.x * v0 + a.y * v1 + a.z * v2 + a.w * v3;
            uint32_t h0, l0, h1, l1;
            cvt_pair(a.x, a.y, h0, l0);
            cvt_pair(a.z, a.w, h1, l1);
            int wbase = row * APADW + (skk >> 1);
            *(uint2*)(ahi + wbase) = make_uint2(h0, h1);
            *(uint2*)(alo + wbase) = make_uint2(l0, l1);
        }
    };

    load_chunk(0);
    store_chunk(0, 0);
    __syncthreads();

    #pragma unroll 1
    for (int c = 0; c < 8; ++c) {
        if (c < 7) load_chunk((c + 1) * 32);    // LDGs in flight during MMA

        const uint32_t* ahi = sm + SM_A_W + (c & 1) * ABUF_W;
        const uint32_t* alo = ahi + 2560;
        #pragma unroll
        for (int ksi = 0; ksi < 2; ++ksi) {
            uint32_t ah[4][4], al[4][4];
            #pragma unroll
            for (int mt = 0; mt < 4; mt++) {
                int r0 = wr * 64 + mt * 16 + lg;
                int w0 = r0 * APADW + ksi * 8 + lq;
                int w1 = (r0 + 8) * APADW + ksi * 8 + lq;
                ah[mt][0] = ahi[w0];
                ah[mt][1] = ahi[w1];
                ah[mt][2] = ahi[w0 + 4];
                ah[mt][3] = ahi[w1 + 4];
                al[mt][0] = alo[w0];
                al[mt][1] = alo[w1];
                al[mt][2] = alo[w0 + 4];
                al[mt][3] = alo[w1 + 4];
            }
            uint32_t bh0[4], bh1[4], bl0[4], bl1[4];
            int kglob = c * 32 + ksi * 16;
            #pragma unroll
            for (int nt = 0; nt < 4; nt++) {
                int n0 = nbase + nt * 8 + lg;
                uint32_t off = (uint32_t)n0 * SPADW + (uint32_t)((kglob + kq) >> 1);
                bh0[nt] = sm[SM_BHI_W + off];
                bh1[nt] = sm[SM_BHI_W + off + 4];
                bl0[nt] = sm[SM_BLO_W + off];
                bl1[nt] = sm[SM_BLO_W + off + 4];
            }
            #pragma unroll
            for (int mt = 0; mt < 4; mt++)
                #pragma unroll
                for (int nt = 0; nt < 4; nt++)
                    mma16816(acc[mt][nt], ah[mt], bh0[nt], bh1[nt]);
            #pragma unroll
            for (int mt = 0; mt < 4; mt++)
                #pragma unroll
                for (int nt = 0; nt < 4; nt++)
                    mma16816(acc[mt][nt], ah[mt], bl0[nt], bl1[nt]);
            #pragma unroll
            for (int mt = 0; mt < 4; mt++)
                #pragma unroll
                for (int nt = 0; nt < 4; nt++)
                    mma16816(acc[mt][nt], al[mt], bh0[nt], bh1[nt]);
        }

        if (c < 7) store_chunk((c + 1) * 32, (c + 1) & 1);
        __syncthreads();
    }

    // sa reduce over the 8 staging threads per row
    {
        float bb2 = b2[0], bb3 = b3[0];
        #pragma unroll
        for (int it = 0; it < 4; ++it) {
            float a1 = s1[it], a2 = s2[it];
            #pragma unroll
            for (int o = 4; o; o >>= 1) {
                a1 += __shfl_xor_sync(0xffffffffu, a1, o);
                a2 += __shfl_xor_sync(0xffffffffu, a2, o);
            }
            if ((tid & 7) == 0) {
                long grow = base + it * 32 + srow_g;
                if (grow < M) {
                    g_sa1[grow] = a1 + bb2;
                    g_sa2[grow] = a2 + bb3;
                }
            }
        }
    }

    // epilogue: dump acc to smem fp32 (reuse B-hi region)
    float* cs = (float*)sm;
    #pragma unroll
    for (int mt = 0; mt < 4; mt++) {
        int r0 = wr * 64 + mt * 16 + lg;
        #pragma unroll
        for (int nt = 0; nt < 4; nt++) {
            int col = nbase + nt * 8 + kq;
            *(float2*)(cs + r0 * CPADW + col) =
                make_float2(acc[mt][nt][0], acc[mt][nt][1]);
            *(float2*)(cs + (r0 + 8) * CPADW + col) =
                make_float2(acc[mt][nt][2], acc[mt][nt][3]);
        }
    }
    __syncthreads();

    // per-row absmax (2 threads per row), scale, int16 quantize
    {
        int row = tid >> 1, half = tid & 1;
        const float* cr = cs + row * CPADW + half * 64;
        float mx = 0.f;
        #pragma unroll 16
        for (int j = 0; j < 64; j++) mx = fmaxf(mx, fabsf(cr[j]));
        ((float*)(sm + SM_PMAX_W))[tid] = mx;
        __syncthreads();
        float rmx = fmaxf(((float*)(sm + SM_PMAX_W))[row * 2],
                          ((float*)(sm + SM_PMAX_W))[row * 2 + 1]);
        rmx = fmaxf(rmx, 1e-30f);
        long grow = base + row;
        if (half == 0 && grow < M) g_vscale[grow] = rmx * (1.0f / 32767.0f);
        float inv = 32767.0f / rmx;
        if (grow < M) {
            uint4* dst = (uint4*)(Q + (grow << 7) + half * 64);
            #pragma unroll
            for (int b8 = 0; b8 < 8; b8++) {
                short sv[8];
                #pragma unroll
                for (int j = 0; j < 8; j++)
                    sv[j] = (short)__float2int_rn(cr[b8 * 8 + j] * inv);
                dst[b8] = *(uint4*)sv;
            }
        }
    }
}

// ---------------- fused softmax + SpMM ----------------
// Weights staged through per-warp smem (broadcast LDS), gather unrolled x4 for MLP.
__device__ __forceinline__ void gather4(const float2* wc, int t, int lane, float4& acc) {
    #pragma unroll
    for (int q = 0; q < 4; q++) {
        float2 e = wc[t + q];
        float wj = e.x;
        int cj = __float_as_int(e.y);
        int2 raw = *(const int2*)(g_qval + ((size_t)cj << 7) + lane * 4);
        short2 p0 = *reinterpret_cast<short2*>(&raw.x);
        short2 p1 = *reinterpret_cast<short2*>(&raw.y);
        acc.x += wj * (float)p0.x;
        acc.y += wj * (float)p0.y;
        acc.z += wj * (float)p1.x;
        acc.w += wj * (float)p1.y;
    }
}

__global__ __launch_bounds__(256) void spmm_kernel(const float* __restrict__ adj,
                                                   const int* __restrict__ col,
                                                   const float* __restrict__ bias,
                                                   float* __restrict__ out) {
    __shared__ float2 s_wc[8][32];
    int warp = threadIdx.x >> 5, lane = threadIdx.x & 31;
    int row = blockIdx.x * 8 + warp;
    if (row >= N_NODES) return;

    int start = g_rowptr[row];
    int end   = g_rowptr[row + 1];
    int deg   = end - start;
    const float4 bv = *(const float4*)(bias + (size_t)row * D_OUT + lane * 4);

    if (deg <= 0) {
        *(float4*)(out + (size_t)row * D_OUT + lane * 4) = bv;
        return;
    }

    float sa1r = g_sa1[row];
    float4 acc = make_float4(0.f, 0.f, 0.f, 0.f);
    float dsum = 0.f;
    float2* wc = s_wc[warp];

    if (deg <= 32) {
        // single-batch fast path: edge stays in registers across max/exp
        int j = start + lane;
        bool v = j < end;
        int c = v ? col[j] : col[start];
        float a = v ? adj[j] : 0.f;
        float e = a * (sa1r + g_sa2[c]);
        e = e > 0.f ? e : 0.2f * e;
        float m = v ? e : -INFINITY;
        #pragma unroll
        for (int o = 16; o; o >>= 1)
            m = fmaxf(m, __shfl_xor_sync(0xffffffffu, m, o));
        float ex = v ? __expf(e - m) : 0.f;
        dsum = ex;
        wc[lane] = make_float2(ex * g_vscale[c], __int_as_float(c));
        __syncwarp();
        int cnt4 = (deg + 3) & ~3;
        for (int t = 0; t < cnt4; t += 4) gather4(wc, t, lane, acc);
    } else {
        // pass 1: segment max
        float m = -INFINITY;
        for (int j = start + lane; j < end; j += 32) {
            float a = adj[j];
            int   c = col[j];
            float e = a * (sa1r + g_sa2[c]);
            e = e > 0.f ? e : 0.2f * e;
            m = fmaxf(m, e);
        }
        #pragma unroll
        for (int o = 16; o; o >>= 1)
            m = fmaxf(m, __shfl_xor_sync(0xffffffffu, m, o));

        // pass 2: staged weights + unrolled gather
        for (int b = start; b < end; b += 32) {
            int j = b + lane;
            bool v = j < end;
            int c = v ? col[j] : col[start];
            float a = v ? adj[j] : 0.f;
            float e = a * (sa1r + g_sa2[c]);
            e = e > 0.f ? e : 0.2f * e;
            float ex = v ? __expf(e - m) : 0.f;
            dsum += ex;
            wc[lane] = make_float2(ex * g_vscale[c], __int_as_float(c));
            __syncwarp();
            int cnt4 = (min(32, end - b) + 3) & ~3;
            for (int t = 0; t < cnt4; t += 4) gather4(wc, t, lane, acc);
            __syncwarp();
        }
    }

    #pragma unroll
    for (int o = 16; o; o >>= 1)
        dsum += __shfl_xor_sync(0xffffffffu, dsum, o);
    if (dsum <= 0.f) dsum = 1.0f;
    float inv = 1.0f / dsum;

    float4 ov;
    ov.x = acc.x * inv + bv.x;
    ov.y = acc.y * inv + bv.y;
    ov.z = acc.z * inv + bv.z;
    ov.w = acc.w * inv + bv.w;
    *(float4*)(out + (size_t)row * D_OUT + lane * 4) = ov;
}

// ---------------- launch ----------------
extern "C" void kernel_launch(void* const* d_in, const int* in_sizes, int n_in,
                              void* d_out, int out_size) {
    const float* x        = (const float*)d_in[0];
    const float* adj_val  = (const float*)d_in[1];
    const float* W1       = (const float*)d_in[2];
    const float* w2       = (const float*)d_in[3];
    const float* b2       = (const float*)d_in[4];
    const float* w3       = (const float*)d_in[5];
    const float* b3       = (const float*)d_in[6];
    const float* kern     = (const float*)d_in[7];
    const float* bias     = (const float*)d_in[8];
    const int*   edge_row = (const int*)d_in[9];
    const int*   edge_col = (const int*)d_in[10];
    float* out = (float*)d_out;

    short* qval;
    cudaGetSymbolAddress((void**)&qval, g_qval);

    cudaFuncSetAttribute(mma_gemm, cudaFuncAttributeMaxDynamicSharedMemorySize, SMEM_BYTES);

    prep_kernel<<<(F_IN * D_OUT + 255) / 256, 256>>>(kern, W1, w2, w3);
    rowptr_kernel<<<(E_EDGES + 1 + 255) / 256, 256>>>(edge_row);
    mma_gemm<<<(N_NODES + 127) / 128, 256, SMEM_BYTES>>>(x, qval, b2, b3, N_NODES);
    spmm_kernel<<<(N_NODES + 7) / 8, 256>>>(adj_val, edge_col, bias, out);
}